// round 2
// baseline (speedup 1.0000x reference)
#include <cuda_runtime.h>

#define NN 8192
#define CC 128

// Scratch for Chebyshev terms (allocation-free rule: __device__ globals)
__device__ float g_T1[NN * CC];
__device__ float g_T2[NN * CC];

// C[M x CC] = alpha * A(M x K) @ B(K x CC) + beta * D(M x CC)
// Tiling: BM=128, BN=64, BK=16; 256 threads; each thread 8x4 micro-tile.
__global__ __launch_bounds__(256)
void gemm_big(const float* __restrict__ A, const float* __restrict__ B,
              const float* __restrict__ D, float* __restrict__ Cmat,
              int K, float alpha, float beta)
{
    const int BM = 128, BN = 64, BK = 16;
    __shared__ float As[BK][BM];  // transposed A tile: As[k][m]
    __shared__ float Bs[BK][BN];  // Bs[k][n]

    const int tid = threadIdx.x;
    const int tx = tid & 15;       // 0..15 -> 64 cols (4 each)
    const int ty = tid >> 4;       // 0..15 -> 128 rows (8 each)
    const int rowBase = blockIdx.x * BM;
    const int colBase = blockIdx.y * BN;

    float acc[8][4];
#pragma unroll
    for (int i = 0; i < 8; i++)
#pragma unroll
        for (int j = 0; j < 4; j++) acc[i][j] = 0.0f;

    for (int k0 = 0; k0 < K; k0 += BK) {
        // Load A tile 128x16 (512 float4s, 2 per thread), store transposed.
#pragma unroll
        for (int i = 0; i < 2; i++) {
            int f  = tid * 2 + i;
            int r  = f >> 2;       // 0..127
            int cg = f & 3;        // 0..3
            float4 v = *(const float4*)(A + (size_t)(rowBase + r) * K + k0 + cg * 4);
            As[cg * 4 + 0][r] = v.x;
            As[cg * 4 + 1][r] = v.y;
            As[cg * 4 + 2][r] = v.z;
            As[cg * 4 + 3][r] = v.w;
        }
        // Load B tile 16x64 (256 float4s, 1 per thread).
        {
            int r  = tid >> 4;     // 0..15
            int cg = tid & 15;     // 0..15
            float4 v = *(const float4*)(B + (size_t)(k0 + r) * CC + colBase + cg * 4);
            *(float4*)(&Bs[r][cg * 4]) = v;
        }
        __syncthreads();

#pragma unroll
        for (int kk = 0; kk < BK; kk++) {
            float4 a0 = *(const float4*)(&As[kk][ty * 8 + 0]);
            float4 a1 = *(const float4*)(&As[kk][ty * 8 + 4]);
            float4 b0 = *(const float4*)(&Bs[kk][tx * 4]);
            float a[8] = {a0.x, a0.y, a0.z, a0.w, a1.x, a1.y, a1.z, a1.w};
            float b[4] = {b0.x, b0.y, b0.z, b0.w};
#pragma unroll
            for (int i = 0; i < 8; i++)
#pragma unroll
                for (int j = 0; j < 4; j++) acc[i][j] += a[i] * b[j];
        }
        __syncthreads();
    }

    // Epilogue: alpha*acc (+ beta*D), float4 stores.
#pragma unroll
    for (int i = 0; i < 8; i++) {
        int r = rowBase + ty * 8 + i;
        size_t off = (size_t)r * CC + colBase + tx * 4;
        float4 v;
        v.x = alpha * acc[i][0];
        v.y = alpha * acc[i][1];
        v.z = alpha * acc[i][2];
        v.w = alpha * acc[i][3];
        if (D) {
            float4 d = *(const float4*)(D + off);
            v.x += beta * d.x; v.y += beta * d.y;
            v.z += beta * d.z; v.w += beta * d.w;
        }
        *(float4*)(Cmat + off) = v;
    }
}

// out = x@W0^T + T1@W1^T + T2@W2^T
// Per block: 64 rows x 128 cols; 256 threads, 8x4 micro-tile; K=128 per term.
__global__ __launch_bounds__(256)
void cheb_out(const float* __restrict__ x, const float* __restrict__ W,
              float* __restrict__ out)
{
    const int BM = 64, BK = 16;
    __shared__ float As[BK][BM];   // As[k][m]
    __shared__ float Ws[BK][CC];   // Ws[k][n] = W[j][n][k]

    const int tid = threadIdx.x;
    const int tx = tid & 31;       // 0..31 -> 128 cols (4 each)
    const int ty = tid >> 5;       // 0..7  -> 64 rows (8 each)
    const int rowBase = blockIdx.x * BM;

    float acc[8][4];
#pragma unroll
    for (int i = 0; i < 8; i++)
#pragma unroll
        for (int j = 0; j < 4; j++) acc[i][j] = 0.0f;

    const float* Amats[3] = {x, g_T1, g_T2};

    for (int jmat = 0; jmat < 3; jmat++) {
        const float* A  = Amats[jmat];
        const float* Wj = W + (size_t)jmat * CC * CC;
        for (int k0 = 0; k0 < CC; k0 += BK) {
            // A tile 64x16: 256 float4s, 1 per thread, transposed store.
            {
                int r  = tid >> 2;   // 0..63
                int cg = tid & 3;    // 0..3
                float4 v = *(const float4*)(A + (size_t)(rowBase + r) * CC + k0 + cg * 4);
                As[cg * 4 + 0][r] = v.x;
                As[cg * 4 + 1][r] = v.y;
                As[cg * 4 + 2][r] = v.z;
                As[cg * 4 + 3][r] = v.w;
            }
            // W tile: Ws[k][n] = Wj[n*CC + k0 + k]; 512 float4s, 2 per thread.
#pragma unroll
            for (int i = 0; i < 2; i++) {
                int f  = tid * 2 + i;
                int n  = f >> 2;     // 0..127
                int cg = f & 3;      // 0..3
                float4 v = *(const float4*)(Wj + (size_t)n * CC + k0 + cg * 4);
                Ws[cg * 4 + 0][n] = v.x;
                Ws[cg * 4 + 1][n] = v.y;
                Ws[cg * 4 + 2][n] = v.z;
                Ws[cg * 4 + 3][n] = v.w;
            }
            __syncthreads();

#pragma unroll
            for (int kk = 0; kk < BK; kk++) {
                float4 a0 = *(const float4*)(&As[kk][ty * 8 + 0]);
                float4 a1 = *(const float4*)(&As[kk][ty * 8 + 4]);
                float4 b0 = *(const float4*)(&Ws[kk][tx * 4]);
                float a[8] = {a0.x, a0.y, a0.z, a0.w, a1.x, a1.y, a1.z, a1.w};
                float b[4] = {b0.x, b0.y, b0.z, b0.w};
#pragma unroll
                for (int i = 0; i < 8; i++)
#pragma unroll
                    for (int j = 0; j < 4; j++) acc[i][j] += a[i] * b[j];
            }
            __syncthreads();
        }
    }

#pragma unroll
    for (int i = 0; i < 8; i++) {
        int r = rowBase + ty * 8 + i;
        size_t off = (size_t)r * CC + tx * 4;
        float4 v = {acc[i][0], acc[i][1], acc[i][2], acc[i][3]};
        *(float4*)(out + off) = v;
    }
}

extern "C" void kernel_launch(void* const* d_in, const int* in_sizes, int n_in,
                              void* d_out, int out_size)
{
    // Identify inputs by element count (robust to metadata ordering):
    //   x: 8192*128 = 1048576, L: 8192*8192 = 67108864, W: 3*128*128 = 49152
    const float* x = nullptr;
    const float* L = nullptr;
    const float* W = nullptr;
    for (int i = 0; i < n_in; i++) {
        long long sz = in_sizes[i];
        if (sz == (long long)NN * NN)       L = (const float*)d_in[i];
        else if (sz == 3LL * CC * CC)       W = (const float*)d_in[i];
        else if (sz == (long long)NN * CC)  x = (const float*)d_in[i];
    }
    float* out = (float*)d_out;

    void *pT1 = nullptr, *pT2 = nullptr;
    cudaGetSymbolAddress(&pT1, g_T1);
    cudaGetSymbolAddress(&pT2, g_T2);
    float* T1 = (float*)pT1;
    float* T2 = (float*)pT2;

    dim3 gridBig(NN / 128, CC / 64);  // 64 x 2 = 128 blocks
    // T1 = L @ x
    gemm_big<<<gridBig, 256>>>(L, x, nullptr, T1, NN, 1.0f, 0.0f);
    // T2 = 2*(L @ T1) - x
    gemm_big<<<gridBig, 256>>>(L, T1, x, T2, NN, 2.0f, -1.0f);
    // out = x@W0^T + T1@W1^T + T2@W2^T
    cheb_out<<<NN / 64, 256>>>(x, W, out);
}

// round 4
// speedup vs baseline: 5.5170x; 5.5170x over previous
#include <cuda_runtime.h>
#include <cuda_bf16.h>
#include <cstdint>

#define NN 8192
#define CC 128

#if defined(__CUDA_ARCH_FEAT_SM103_ALL) || defined(__CUDA_ARCH_FEAT_SM100_ALL) || defined(__CUDA_ARCH_FEAT_SM101_ALL)
#define HAS_TCGEN05 1
#else
#define HAS_TCGEN05 0
#endif

// ---------------- scratch (__device__ globals: allocation-free rule) --------
__device__ float g_T1[NN * CC];
__device__ float g_T2[NN * CC];
__device__ float g_P[2 * NN * CC];                 // split-K partials
__device__ __nv_bfloat16 g_Bt_hi[CC * NN];         // transposed B operand, hi
__device__ __nv_bfloat16 g_Bt_lo[CC * NN];         // transposed B operand, lo

// ---------------- PTX helpers (safe on all targets) -------------------------
__device__ __forceinline__ uint32_t smem_u32(const void* p) {
    uint32_t a;
    asm("{ .reg .u64 t; cvta.to.shared.u64 t, %1; cvt.u32.u64 %0, t; }" : "=r"(a) : "l"(p));
    return a;
}

#define MBARRIER_INIT(addr, cnt) \
    asm volatile("mbarrier.init.shared.b64 [%0], %1;" :: "r"((uint32_t)(addr)), "r"((uint32_t)(cnt)) : "memory")

#define MBARRIER_WAIT_PARITY(addr, parity) do {                                    \
    uint32_t _m = (uint32_t)(addr), _p = (uint32_t)(parity), _d;                   \
    asm volatile("{\n\t.reg .pred p;\n\t"                                          \
        "mbarrier.try_wait.parity.acquire.cta.shared::cta.b64 p, [%1], %2;\n\t"    \
        "selp.b32 %0, 1, 0, p;\n\t}" : "=r"(_d) : "r"(_m), "r"(_p) : "memory");    \
    if (!_d) {                                                                     \
        asm volatile("{\n\t.reg .pred P1;\n\t"                                     \
            "WL_%=:\n\t"                                                           \
            "mbarrier.try_wait.parity.acquire.cta.shared::cta.b64 P1, [%0], %1, 0x989680;\n\t" \
            "@P1 bra.uni WD_%=;\n\tbra.uni WL_%=;\n\tWD_%=:\n\t}"                  \
            :: "r"(_m), "r"(_p) : "memory");                                       \
    }                                                                              \
} while (0)

#define FENCE_PROXY_ASYNC()    asm volatile("fence.proxy.async.shared::cta;" ::: "memory")

// SW128 descriptor: layout=2, version=1, SBO=64, LBO=1
static constexpr uint64_t DESC_BASE_SW128 =
    (uint64_t(2) << 61) | (uint64_t(1) << 46) | (uint64_t(64) << 32) | (uint64_t(1) << 16);
#define MAKE_DESC(addr) (DESC_BASE_SW128 | ((uint64_t)((addr) >> 4) & 0x3FFF))

__device__ __forceinline__ uint32_t sw128(uint32_t o) { return o ^ ((o >> 3) & 0x70); }

// idesc: fp32 accum, bf16 A/B, M=128, N=128  (pattern verified vs 0x8080490 example)
static constexpr uint32_t IDESC =
    (1u << 4) | (1u << 7) | (1u << 10) | ((128u / 8) << 17) | ((128u / 16) << 24);

// ---------------- smem layout ------------------------------------------------
// [0] tmem ptr | [16,32) mbar[2] | [1024+) 2 stages x (A_hi|A_lo|B_hi|B_lo) 16K each
#define SM_TMEM   0
#define SM_MBAR   16
#define SM_TILES  1024
#define STAGE_SZ  65536
#define SMEM_TOTAL (SM_TILES + 2 * STAGE_SZ)

// ---------------- tensor-core GEMM: P[khalf] = L[tile] @ Bt^T ----------------
// grid (64, 2); 256 threads. Per CTA: 128 rows x 128 cols, K half = 4096.
__global__ __launch_bounds__(256, 1)
void gemm_tc(const float* __restrict__ L,
             const __nv_bfloat16* __restrict__ Bhi,
             const __nv_bfloat16* __restrict__ Blo,
             float* __restrict__ P)
{
#if HAS_TCGEN05
    extern __shared__ char smem[];
    const uint32_t sbase = smem_u32(smem);
    const int tid = threadIdx.x;
    const int wid = tid >> 5, lid = tid & 31;
    const int mBase = blockIdx.x * 128;
    const int khalf = blockIdx.y;
    const int kStart = khalf * 4096;

    if (wid == 0)
        asm volatile("tcgen05.alloc.cta_group::1.sync.aligned.shared::cta.b32 [%0], %1;"
                     :: "r"(sbase + SM_TMEM), "r"(128u) : "memory");
    if (tid == 0) { MBARRIER_INIT(sbase + SM_MBAR, 1); MBARRIER_INIT(sbase + SM_MBAR + 8, 1); }
    __syncthreads();
    uint32_t tmem;
    asm volatile("ld.shared.b32 %0, [%1];" : "=r"(tmem) : "r"(sbase + SM_TMEM));

    int ph[2] = {0, 0};
    const int NCHUNK = 4096 / 64;

    for (int c = 0; c < NCHUNK; c++) {
        const int s = c & 1;
        const uint32_t stg = sbase + SM_TILES + s * STAGE_SZ;
        char* stgp = smem + SM_TILES + s * STAGE_SZ;
        const int kBase = kStart + c * 64;

        if (c >= 2) { MBARRIER_WAIT_PARITY(sbase + SM_MBAR + 8 * s, ph[s]); ph[s] ^= 1; }

        // ---- A: L fp32 -> bf16 hi/lo, SW128-swizzled, 128 rows x 64 k -------
#pragma unroll
        for (int i = 0; i < 8; i++) {
            int f = tid + i * 256;            // 0..2047
            int row = f >> 4, cg = f & 15;
            float4 v = *(const float4*)(L + (size_t)(mBase + row) * NN + kBase + cg * 4);
            __nv_bfloat16 h0 = __float2bfloat16(v.x), h1 = __float2bfloat16(v.y);
            __nv_bfloat16 h2 = __float2bfloat16(v.z), h3 = __float2bfloat16(v.w);
            __nv_bfloat16 l0 = __float2bfloat16(v.x - __bfloat162float(h0));
            __nv_bfloat16 l1 = __float2bfloat16(v.y - __bfloat162float(h1));
            __nv_bfloat16 l2 = __float2bfloat16(v.z - __bfloat162float(h2));
            __nv_bfloat16 l3 = __float2bfloat16(v.w - __bfloat162float(h3));
            uint2 hp, lp;
            hp.x = (uint32_t)__bfloat16_as_ushort(h0) | ((uint32_t)__bfloat16_as_ushort(h1) << 16);
            hp.y = (uint32_t)__bfloat16_as_ushort(h2) | ((uint32_t)__bfloat16_as_ushort(h3) << 16);
            lp.x = (uint32_t)__bfloat16_as_ushort(l0) | ((uint32_t)__bfloat16_as_ushort(l1) << 16);
            lp.y = (uint32_t)__bfloat16_as_ushort(l2) | ((uint32_t)__bfloat16_as_ushort(l3) << 16);
            uint32_t off = sw128((uint32_t)(row * 128 + cg * 8));
            *(uint2*)(stgp + off) = hp;             // A_hi
            *(uint2*)(stgp + 16384 + off) = lp;     // A_lo
        }
        // ---- B: pre-split bf16 [c][k], 128 rows x 64 k ----------------------
#pragma unroll
        for (int i = 0; i < 4; i++) {
            int f = tid + i * 256;            // 0..1023
            int row = f >> 3, g = f & 7;
            size_t src = (size_t)row * NN + kBase + g * 8;
            uint4 vh = *(const uint4*)(Bhi + src);
            uint4 vl = *(const uint4*)(Blo + src);
            uint32_t off = sw128((uint32_t)(row * 128 + g * 16));
            *(uint4*)(stgp + 32768 + off) = vh;     // B_hi
            *(uint4*)(stgp + 49152 + off) = vl;     // B_lo
        }
        __syncthreads();

        if (tid == 0) {
            FENCE_PROXY_ASYNC();
            uint64_t dAh = MAKE_DESC(stg);
            uint64_t dAl = MAKE_DESC(stg + 16384);
            uint64_t dBh = MAKE_DESC(stg + 32768);
            uint64_t dBl = MAKE_DESC(stg + 49152);
#pragma unroll
            for (int ks = 0; ks < 4; ks++) {
                uint32_t en = (c > 0 || ks > 0) ? 1u : 0u;
                asm volatile(
                    "{\n\t.reg .pred p;\n\tsetp.ne.u32 p, %5, 0;\n\t"
                    "tcgen05.mma.cta_group::1.kind::f16 [%0], %1, %2, %3, {%4,%4,%4,%4}, p;\n\t}"
                    :: "r"(tmem), "l"(dAh + ks * 2), "l"(dBh + ks * 2), "r"(IDESC), "r"(0u), "r"(en) : "memory");
            }
#pragma unroll
            for (int ks = 0; ks < 4; ks++)
                asm volatile(
                    "{\n\t.reg .pred p;\n\tsetp.ne.u32 p, %5, 0;\n\t"
                    "tcgen05.mma.cta_group::1.kind::f16 [%0], %1, %2, %3, {%4,%4,%4,%4}, p;\n\t}"
                    :: "r"(tmem), "l"(dAh + ks * 2), "l"(dBl + ks * 2), "r"(IDESC), "r"(0u), "r"(1u) : "memory");
#pragma unroll
            for (int ks = 0; ks < 4; ks++)
                asm volatile(
                    "{\n\t.reg .pred p;\n\tsetp.ne.u32 p, %5, 0;\n\t"
                    "tcgen05.mma.cta_group::1.kind::f16 [%0], %1, %2, %3, {%4,%4,%4,%4}, p;\n\t}"
                    :: "r"(tmem), "l"(dAl + ks * 2), "l"(dBh + ks * 2), "r"(IDESC), "r"(0u), "r"(1u) : "memory");
            asm volatile("tcgen05.commit.cta_group::1.mbarrier::arrive::one.shared::cluster.b64 [%0];"
                         :: "r"(sbase + SM_MBAR + 8 * s) : "memory");
        }
    }

    MBARRIER_WAIT_PARITY(sbase + SM_MBAR + 0, ph[0]);
    MBARRIER_WAIT_PARITY(sbase + SM_MBAR + 8, ph[1]);
    asm volatile("tcgen05.fence::after_thread_sync;" ::: "memory");

    // epilogue: warps 0-3 read their subpartitions (128 rows x 128 fp32 cols)
    if (wid < 4) {
        const int m = mBase + wid * 32 + lid;
        float* dst = P + (size_t)khalf * NN * CC + (size_t)m * CC;
#pragma unroll
        for (int cb = 0; cb < 128; cb += 32) {
            uint32_t r[32];
            asm volatile("tcgen05.ld.sync.aligned.32x32b.x32.b32 "
                "{%0,%1,%2,%3,%4,%5,%6,%7,%8,%9,%10,%11,%12,%13,%14,%15,"
                "%16,%17,%18,%19,%20,%21,%22,%23,%24,%25,%26,%27,%28,%29,%30,%31}, [%32];"
                : "=r"(r[0]),"=r"(r[1]),"=r"(r[2]),"=r"(r[3]),"=r"(r[4]),"=r"(r[5]),"=r"(r[6]),"=r"(r[7]),
                  "=r"(r[8]),"=r"(r[9]),"=r"(r[10]),"=r"(r[11]),"=r"(r[12]),"=r"(r[13]),"=r"(r[14]),"=r"(r[15]),
                  "=r"(r[16]),"=r"(r[17]),"=r"(r[18]),"=r"(r[19]),"=r"(r[20]),"=r"(r[21]),"=r"(r[22]),"=r"(r[23]),
                  "=r"(r[24]),"=r"(r[25]),"=r"(r[26]),"=r"(r[27]),"=r"(r[28]),"=r"(r[29]),"=r"(r[30]),"=r"(r[31])
                : "r"(tmem + cb));
            asm volatile("tcgen05.wait::ld.sync.aligned;" ::: "memory");
#pragma unroll
            for (int j = 0; j < 32; j += 4) {
                float4 v = { __uint_as_float(r[j]), __uint_as_float(r[j + 1]),
                             __uint_as_float(r[j + 2]), __uint_as_float(r[j + 3]) };
                *(float4*)(dst + cb + j) = v;
            }
        }
        asm volatile("tcgen05.fence::before_thread_sync;" ::: "memory");
    }
    __syncthreads();
    if (wid == 0) {
        asm volatile("tcgen05.relinquish_alloc_permit.cta_group::1.sync.aligned;");
        asm volatile("tcgen05.dealloc.cta_group::1.sync.aligned.b32 %0, %1;" :: "r"(tmem), "r"(128u));
    }
#else
    // Fallback for the non-'a' PTX pass (never executed on GB300: cubin is sm_103a).
    const int tid = threadIdx.x;
    const int mBase = blockIdx.x * 128;
    const int khalf = blockIdx.y;
    const int kStart = khalf * 4096;
    for (int e = tid; e < 128 * 128; e += 256) {
        int m = mBase + (e >> 7), c = e & 127;
        float acc = 0.0f;
        const float* Lr = L + (size_t)m * NN + kStart;
        const __nv_bfloat16* bh = Bhi + (size_t)c * NN + kStart;
        const __nv_bfloat16* bl = Blo + (size_t)c * NN + kStart;
        for (int k = 0; k < 4096; k++)
            acc += Lr[k] * (__bfloat162float(bh[k]) + __bfloat162float(bl[k]));
        P[(size_t)khalf * NN * CC + (size_t)m * CC + c] = acc;
    }
#endif
}

// ---------------- transpose-split: Bt = split(x^T)  (coalesced) --------------
// grid (NN/32, CC/32), block (32, 8)
__global__ void convert_x(const float* __restrict__ x)
{
    __shared__ float tile[32][33];
    const int n0 = blockIdx.x * 32, c0 = blockIdx.y * 32;
    const int tx = threadIdx.x, ty = threadIdx.y;
#pragma unroll
    for (int r = 0; r < 4; r++) {
        int row = ty + 8 * r;
        tile[row][tx] = x[(size_t)(n0 + row) * CC + c0 + tx];
    }
    __syncthreads();
#pragma unroll
    for (int r = 0; r < 4; r++) {
        int crow = ty + 8 * r;
        float v = tile[tx][crow];                    // = x[n0+tx][c0+crow]
        __nv_bfloat16 h = __float2bfloat16(v);
        size_t o = (size_t)(c0 + crow) * NN + n0 + tx;
        g_Bt_hi[o] = h;
        g_Bt_lo[o] = __float2bfloat16(v - __bfloat162float(h));
    }
}

// ---------------- T1 = P0+P1 (coalesced) + transposed split ------------------
__global__ void reduce1()
{
    __shared__ float tile[32][33];
    const int n0 = blockIdx.x * 32, c0 = blockIdx.y * 32;
    const int tx = threadIdx.x, ty = threadIdx.y;
#pragma unroll
    for (int r = 0; r < 4; r++) {
        int row = ty + 8 * r;
        size_t o = (size_t)(n0 + row) * CC + c0 + tx;
        float v = g_P[o] + g_P[(size_t)NN * CC + o];
        g_T1[o] = v;
        tile[row][tx] = v;
    }
    __syncthreads();
#pragma unroll
    for (int r = 0; r < 4; r++) {
        int crow = ty + 8 * r;
        float v = tile[tx][crow];
        __nv_bfloat16 h = __float2bfloat16(v);
        size_t o = (size_t)(c0 + crow) * NN + n0 + tx;
        g_Bt_hi[o] = h;
        g_Bt_lo[o] = __float2bfloat16(v - __bfloat162float(h));
    }
}

// ---------------- T2 = 2*(P0+P1) - x (coalesced) -----------------------------
__global__ void reduce2(const float* __restrict__ x)
{
    int idx = blockIdx.x * blockDim.x + threadIdx.x;
    if (idx >= NN * CC) return;
    g_T2[idx] = 2.0f * (g_P[idx] + g_P[NN * CC + idx]) - x[idx];
}

// ---------------- out = x@W0^T + T1@W1^T + T2@W2^T (SIMT, tiny) --------------
__global__ __launch_bounds__(256)
void cheb_out(const float* __restrict__ x, const float* __restrict__ W,
              float* __restrict__ out)
{
    const int BK = 16;
    __shared__ float As[BK][64];
    __shared__ float Ws[BK][CC];

    const int tid = threadIdx.x;
    const int tx = tid & 31, ty = tid >> 5;
    const int rowBase = blockIdx.x * 64;

    float acc[8][4];
#pragma unroll
    for (int i = 0; i < 8; i++)
#pragma unroll
        for (int j = 0; j < 4; j++) acc[i][j] = 0.0f;

    const float* Amats[3] = {x, g_T1, g_T2};
    for (int jm = 0; jm < 3; jm++) {
        const float* A = Amats[jm];
        const float* Wj = W + (size_t)jm * CC * CC;
        for (int k0 = 0; k0 < CC; k0 += BK) {
            {
                int r = tid >> 2, cg = tid & 3;
                float4 v = *(const float4*)(A + (size_t)(rowBase + r) * CC + k0 + cg * 4);
                As[cg * 4 + 0][r] = v.x; As[cg * 4 + 1][r] = v.y;
                As[cg * 4 + 2][r] = v.z; As[cg * 4 + 3][r] = v.w;
            }
#pragma unroll
            for (int i = 0; i < 2; i++) {
                int f = tid * 2 + i;
                int n = f >> 2, cg = f & 3;
                float4 v = *(const float4*)(Wj + (size_t)n * CC + k0 + cg * 4);
                Ws[cg * 4 + 0][n] = v.x; Ws[cg * 4 + 1][n] = v.y;
                Ws[cg * 4 + 2][n] = v.z; Ws[cg * 4 + 3][n] = v.w;
            }
            __syncthreads();
#pragma unroll
            for (int kk = 0; kk < BK; kk++) {
                float4 a0 = *(const float4*)(&As[kk][ty * 8 + 0]);
                float4 a1 = *(const float4*)(&As[kk][ty * 8 + 4]);
                float4 b0 = *(const float4*)(&Ws[kk][tx * 4]);
                float a[8] = {a0.x, a0.y, a0.z, a0.w, a1.x, a1.y, a1.z, a1.w};
                float b[4] = {b0.x, b0.y, b0.z, b0.w};
#pragma unroll
                for (int i = 0; i < 8; i++)
#pragma unroll
                    for (int j = 0; j < 4; j++) acc[i][j] += a[i] * b[j];
            }
            __syncthreads();
        }
    }
#pragma unroll
    for (int i = 0; i < 8; i++) {
        size_t off = (size_t)(rowBase + ty * 8 + i) * CC + tx * 4;
        float4 v = {acc[i][0], acc[i][1], acc[i][2], acc[i][3]};
        *(float4*)(out + off) = v;
    }
}

// ---------------- launch -----------------------------------------------------
extern "C" void kernel_launch(void* const* d_in, const int* in_sizes, int n_in,
                              void* d_out, int out_size)
{
    const float *x = nullptr, *L = nullptr, *W = nullptr;
    for (int i = 0; i < n_in; i++) {
        long long sz = in_sizes[i];
        if (sz == (long long)NN * NN)      L = (const float*)d_in[i];
        else if (sz == 3LL * CC * CC)      W = (const float*)d_in[i];
        else if (sz == (long long)NN * CC) x = (const float*)d_in[i];
    }
    float* out = (float*)d_out;

    void* pP  = nullptr; cudaGetSymbolAddress(&pP,  g_P);
    void* pBh = nullptr; cudaGetSymbolAddress(&pBh, g_Bt_hi);
    void* pBl = nullptr; cudaGetSymbolAddress(&pBl, g_Bt_lo);

    cudaFuncSetAttribute(gemm_tc, cudaFuncAttributeMaxDynamicSharedMemorySize, SMEM_TOTAL);

    const int NELEM = NN * CC;
    dim3 gGemm(64, 2);
    dim3 gTr(NN / 32, CC / 32);
    dim3 bTr(32, 8);

    convert_x<<<gTr, bTr>>>(x);
    gemm_tc<<<gGemm, 256, SMEM_TOTAL>>>(L, (const __nv_bfloat16*)pBh,
                                        (const __nv_bfloat16*)pBl, (float*)pP);
    reduce1<<<gTr, bTr>>>();
    gemm_tc<<<gGemm, 256, SMEM_TOTAL>>>(L, (const __nv_bfloat16*)pBh,
                                        (const __nv_bfloat16*)pBl, (float*)pP);
    reduce2<<<(NELEM + 511) / 512, 512>>>(x);
    cheb_out<<<NN / 64, 256>>>(x, W, out);
}